// round 2
// baseline (speedup 1.0000x reference)
#include <cuda_runtime.h>
#include <cuda_bf16.h>
#include <stdint.h>
#include <math.h>

#define NN   100000
#define EE   800000
#define DDIM 128
#define NPAD 100096   // 782 * 128
#define NBLK 782

// ---------------- scratch (device globals; no runtime alloc) ----------------
__device__ __align__(256) float g_bufA[(size_t)NPAD * DDIM];
__device__ __align__(256) float g_bufB[(size_t)NPAD * DDIM];
__device__ __align__(256) float g_bufM[(size_t)NPAD * DDIM];
__device__ int   g_deg[NN];
__device__ int   g_rowptr[NN + 1];
__device__ int   g_cursor[NN];
__device__ float g_deginv[NN];
__device__ int   g_colidx[EE];
__device__ int   g_is64;
__device__ __align__(16) __nv_bfloat16 g_Wp_hi[DDIM * DDIM];
__device__ __align__(16) __nv_bfloat16 g_Wp_lo[DDIM * DDIM];
__device__ __align__(16) __nv_bfloat16 g_Wb_hi[3][DDIM * 2 * DDIM];
__device__ __align__(16) __nv_bfloat16 g_Wb_lo[3][DDIM * 2 * DDIM];

// ---------------- edge-index dtype detection ----------------
// If the buffer is int64, words at odd positions (high halves of values in
// [0, N)) are all zero. If int32, odd words are random node ids -> nonzero.
__global__ void k_det_init() { g_is64 = 1; }

__global__ void k_detect(const unsigned* __restrict__ w) {
    int i = blockIdx.x * blockDim.x + threadIdx.x;
    if (i < EE && w[2 * i + 1] != 0u) g_is64 = 0;
}

__device__ __forceinline__ int load_idx(const void* ei, int pos, int is64) {
    if (is64) return (int)((const long long*)ei)[pos];
    return ((const int*)ei)[pos];
}

// ---------------- CSR build ----------------
__global__ void k_zero_deg() {
    int i = blockIdx.x * blockDim.x + threadIdx.x;
    if (i < NN) g_deg[i] = 0;
}

__global__ void k_hist(const void* __restrict__ ei) {
    int e = blockIdx.x * blockDim.x + threadIdx.x;
    if (e < EE) {
        int d = load_idx(ei, EE + e, g_is64);
        if ((unsigned)d < NN) atomicAdd(&g_deg[d], 1);
    }
}

__global__ void k_scan() {
    __shared__ int part[1024];
    const int t = threadIdx.x;
    int lo = t * 98; if (lo > NN) lo = NN;
    int hi = lo + 98; if (hi > NN) hi = NN;
    int s = 0;
    for (int i = lo; i < hi; i++) s += g_deg[i];
    part[t] = s;
    __syncthreads();
    for (int off = 1; off < 1024; off <<= 1) {
        int v = (t >= off) ? part[t - off] : 0;
        __syncthreads();
        part[t] += v;
        __syncthreads();
    }
    int run = (t == 0) ? 0 : part[t - 1];
    for (int i = lo; i < hi; i++) {
        int d = g_deg[i];
        g_rowptr[i] = run;
        g_cursor[i] = run;
        g_deginv[i] = (d > 0) ? 1.0f / (float)d : 0.0f;
        run += d;
    }
    if (t == 1023) g_rowptr[NN] = part[1023];
}

__global__ void k_fill(const void* __restrict__ ei) {
    int e = blockIdx.x * blockDim.x + threadIdx.x;
    if (e < EE) {
        int is64 = g_is64;
        int s = load_idx(ei, e, is64);
        int d = load_idx(ei, EE + e, is64);
        if ((unsigned)d < NN && (unsigned)s < NN) {
            int p = atomicAdd(&g_cursor[d], 1);
            g_colidx[p] = s;
        }
    }
}

// ---------------- scatter-mean as CSR gather-sum (warp per node) ----------------
__global__ void k_aggregate(const float* __restrict__ h, float* __restrict__ mean) {
    int node = (blockIdx.x * blockDim.x + threadIdx.x) >> 5;
    if (node >= NN) return;
    int lane = threadIdx.x & 31;
    int s = g_rowptr[node], e = g_rowptr[node + 1];
    float4 a0 = make_float4(0.f, 0.f, 0.f, 0.f);
    float4 a1 = make_float4(0.f, 0.f, 0.f, 0.f);
    int i = s;
    for (; i + 2 <= e; i += 2) {
        int j0 = g_colidx[i];
        int j1 = g_colidx[i + 1];
        float4 v0 = *(const float4*)(h + (size_t)j0 * DDIM + lane * 4);
        float4 v1 = *(const float4*)(h + (size_t)j1 * DDIM + lane * 4);
        a0.x += v0.x; a0.y += v0.y; a0.z += v0.z; a0.w += v0.w;
        a1.x += v1.x; a1.y += v1.y; a1.z += v1.z; a1.w += v1.w;
    }
    if (i < e) {
        int j0 = g_colidx[i];
        float4 v0 = *(const float4*)(h + (size_t)j0 * DDIM + lane * 4);
        a0.x += v0.x; a0.y += v0.y; a0.z += v0.z; a0.w += v0.w;
    }
    float sc = g_deginv[node];
    float4 r;
    r.x = (a0.x + a1.x) * sc;
    r.y = (a0.y + a1.y) * sc;
    r.z = (a0.z + a1.z) * sc;
    r.w = (a0.w + a1.w) * sc;
    *(float4*)(mean + (size_t)node * DDIM + lane * 4) = r;
}

// ---------------- weight conversion: fp32 -> bf16 hi/lo, laid out [n][k] ----------------
__global__ void k_convert(const float* __restrict__ src, __nv_bfloat16* __restrict__ hi,
                          __nv_bfloat16* __restrict__ lo, int koff, int kstride) {
    int idx = blockIdx.x * blockDim.x + threadIdx.x;
    if (idx >= DDIM * DDIM) return;
    int n = idx >> 7, k = idx & 127;
    float v = src[idx];
    __nv_bfloat16 h = __float2bfloat16(v);
    float r = v - __bfloat162float(h);
    hi[n * kstride + koff + k] = h;
    lo[n * kstride + koff + k] = __float2bfloat16(r);
}

// ---------------- GEMM: C[N,128] = [A0 | A1][N,KH*128] @ B + epilogue ----------------
__device__ __forceinline__ unsigned pack2(__nv_bfloat16 a, __nv_bfloat16 b) {
    __nv_bfloat162 t = __halves2bfloat162(a, b);
    return *reinterpret_cast<unsigned*>(&t);
}

__device__ __forceinline__ void split2(float x, float y, unsigned& hi, unsigned& lo) {
    __nv_bfloat16 hx = __float2bfloat16(x);
    __nv_bfloat16 hy = __float2bfloat16(y);
    hi = pack2(hx, hy);
    lo = pack2(__float2bfloat16(x - __bfloat162float(hx)),
               __float2bfloat16(y - __bfloat162float(hy)));
}

__device__ __forceinline__ void mma_bf16(float (&c)[4], const unsigned (&a)[4],
                                         unsigned b0, unsigned b1) {
    asm volatile(
        "mma.sync.aligned.m16n8k16.row.col.f32.bf16.bf16.f32 "
        "{%0,%1,%2,%3}, {%4,%5,%6,%7}, {%8,%9}, {%0,%1,%2,%3};\n"
        : "+f"(c[0]), "+f"(c[1]), "+f"(c[2]), "+f"(c[3])
        : "r"(a[0]), "r"(a[1]), "r"(a[2]), "r"(a[3]), "r"(b0), "r"(b1));
}

// EPI: 0 = plain store, 1 = relu(acc+bias)+identity, 2 = bias + row L2-normalize
template<int KH, int EPI>
__global__ void __launch_bounds__(128, 2) k_gemm(
    const float* __restrict__ A0, const float* __restrict__ A1,
    const __nv_bfloat16* __restrict__ Bh, const __nv_bfloat16* __restrict__ Bl,
    const float* __restrict__ bias, const float* __restrict__ identity,
    float* __restrict__ out)
{
    constexpr int KFULL = KH * 128;
    const int w = threadIdx.x >> 5;
    const int lane = threadIdx.x & 31;
    const int g = lane >> 2;
    const int tig = lane & 3;
    const int rowbase = blockIdx.x * 128 + w * 32;
    int rr[4] = { rowbase + g, rowbase + g + 8, rowbase + g + 16, rowbase + g + 24 };
    bool pp[4];
#pragma unroll
    for (int i = 0; i < 4; i++) pp[i] = rr[i] < NN;

    float acc[16][2][4];
#pragma unroll
    for (int t = 0; t < 16; t++)
#pragma unroll
        for (int s = 0; s < 2; s++)
#pragma unroll
            for (int i = 0; i < 4; i++) acc[t][s][i] = 0.f;

#pragma unroll
    for (int kh = 0; kh < KH; kh++) {
        const float* A = (kh == 0) ? A0 : A1;
#pragma unroll
        for (int ks = 0; ks < 8; ks++) {
            const int kc = ks * 16 + tig * 2;
            unsigned aH[2][4], aL[2][4];
#pragma unroll
            for (int s = 0; s < 2; s++) {
                float2 z = make_float2(0.f, 0.f);
                float2 v00 = pp[2*s]   ? *(const float2*)(A + (size_t)rr[2*s]   * DDIM + kc)     : z;
                float2 v01 = pp[2*s]   ? *(const float2*)(A + (size_t)rr[2*s]   * DDIM + kc + 8) : z;
                float2 v10 = pp[2*s+1] ? *(const float2*)(A + (size_t)rr[2*s+1] * DDIM + kc)     : z;
                float2 v11 = pp[2*s+1] ? *(const float2*)(A + (size_t)rr[2*s+1] * DDIM + kc + 8) : z;
                split2(v00.x, v00.y, aH[s][0], aL[s][0]);
                split2(v10.x, v10.y, aH[s][1], aL[s][1]);
                split2(v01.x, v01.y, aH[s][2], aL[s][2]);
                split2(v11.x, v11.y, aH[s][3], aL[s][3]);
            }
            const int kb = kh * 128 + ks * 16 + tig * 2;
#pragma unroll
            for (int t = 0; t < 16; t++) {
                const int nr = t * 8 + g;
                const __nv_bfloat16* ph = Bh + nr * KFULL + kb;
                const __nv_bfloat16* pl = Bl + nr * KFULL + kb;
                unsigned bh0 = *(const unsigned*)ph;
                unsigned bh1 = *(const unsigned*)(ph + 8);
                unsigned bl0 = *(const unsigned*)pl;
                unsigned bl1 = *(const unsigned*)(pl + 8);
                mma_bf16(acc[t][0], aH[0], bh0, bh1);
                mma_bf16(acc[t][0], aH[0], bl0, bl1);
                mma_bf16(acc[t][0], aL[0], bh0, bh1);
                mma_bf16(acc[t][1], aH[1], bh0, bh1);
                mma_bf16(acc[t][1], aH[1], bl0, bl1);
                mma_bf16(acc[t][1], aL[1], bh0, bh1);
            }
        }
    }

    if (EPI == 0) {
#pragma unroll
        for (int t = 0; t < 16; t++) {
            const int c = t * 8 + tig * 2;
#pragma unroll
            for (int s = 0; s < 2; s++) {
                if (pp[2*s])
                    *(float2*)(out + (size_t)rr[2*s] * DDIM + c) =
                        make_float2(acc[t][s][0], acc[t][s][1]);
                if (pp[2*s+1])
                    *(float2*)(out + (size_t)rr[2*s+1] * DDIM + c) =
                        make_float2(acc[t][s][2], acc[t][s][3]);
            }
        }
    } else if (EPI == 1) {
#pragma unroll
        for (int t = 0; t < 16; t++) {
            const int c = t * 8 + tig * 2;
            float2 bb = *(const float2*)(bias + c);
#pragma unroll
            for (int s = 0; s < 2; s++) {
                if (pp[2*s]) {
                    float vx = fmaxf(acc[t][s][0] + bb.x, 0.f);
                    float vy = fmaxf(acc[t][s][1] + bb.y, 0.f);
                    float2 id = *(const float2*)(identity + (size_t)rr[2*s] * DDIM + c);
                    *(float2*)(out + (size_t)rr[2*s] * DDIM + c) =
                        make_float2(vx + id.x, vy + id.y);
                }
                if (pp[2*s+1]) {
                    float vx = fmaxf(acc[t][s][2] + bb.x, 0.f);
                    float vy = fmaxf(acc[t][s][3] + bb.y, 0.f);
                    float2 id = *(const float2*)(identity + (size_t)rr[2*s+1] * DDIM + c);
                    *(float2*)(out + (size_t)rr[2*s+1] * DDIM + c) =
                        make_float2(vx + id.x, vy + id.y);
                }
            }
        }
    } else {
        float ss[4] = {0.f, 0.f, 0.f, 0.f};
#pragma unroll
        for (int t = 0; t < 16; t++) {
            const int c = t * 8 + tig * 2;
            float2 bb = *(const float2*)(bias + c);
#pragma unroll
            for (int s = 0; s < 2; s++) {
                acc[t][s][0] += bb.x; acc[t][s][1] += bb.y;
                acc[t][s][2] += bb.x; acc[t][s][3] += bb.y;
                ss[2*s]   += acc[t][s][0] * acc[t][s][0] + acc[t][s][1] * acc[t][s][1];
                ss[2*s+1] += acc[t][s][2] * acc[t][s][2] + acc[t][s][3] * acc[t][s][3];
            }
        }
#pragma unroll
        for (int i = 0; i < 4; i++) {
            ss[i] += __shfl_xor_sync(0xffffffffu, ss[i], 1);
            ss[i] += __shfl_xor_sync(0xffffffffu, ss[i], 2);
            ss[i] = 1.f / fmaxf(sqrtf(ss[i]), 1e-12f);
        }
#pragma unroll
        for (int t = 0; t < 16; t++) {
            const int c = t * 8 + tig * 2;
#pragma unroll
            for (int s = 0; s < 2; s++) {
                if (pp[2*s])
                    *(float2*)(out + (size_t)rr[2*s] * DDIM + c) =
                        make_float2(acc[t][s][0] * ss[2*s], acc[t][s][1] * ss[2*s]);
                if (pp[2*s+1])
                    *(float2*)(out + (size_t)rr[2*s+1] * DDIM + c) =
                        make_float2(acc[t][s][2] * ss[2*s+1], acc[t][s][3] * ss[2*s+1]);
            }
        }
    }
}

// ---------------- launch ----------------
extern "C" void kernel_launch(void* const* d_in, const int* in_sizes, int n_in,
                              void* d_out, int out_size) {
    const float* x      = (const float*)d_in[0];
    const void*  ei     = d_in[1];
    const float* W_proj = (const float*)d_in[2];
    const float* W1_l   = (const float*)d_in[3];
    const float* b1     = (const float*)d_in[4];
    const float* W1_r   = (const float*)d_in[5];
    const float* W2_l   = (const float*)d_in[6];
    const float* b2     = (const float*)d_in[7];
    const float* W2_r   = (const float*)d_in[8];
    const float* W3_l   = (const float*)d_in[9];
    const float* b3     = (const float*)d_in[10];
    const float* W3_r   = (const float*)d_in[11];
    float* out = (float*)d_out;

    float *bufA, *bufB, *bufM;
    __nv_bfloat16 *Wph, *Wpl, *Wbh, *Wbl;
    cudaGetSymbolAddress((void**)&bufA, g_bufA);
    cudaGetSymbolAddress((void**)&bufB, g_bufB);
    cudaGetSymbolAddress((void**)&bufM, g_bufM);
    cudaGetSymbolAddress((void**)&Wph,  g_Wp_hi);
    cudaGetSymbolAddress((void**)&Wpl,  g_Wp_lo);
    cudaGetSymbolAddress((void**)&Wbh,  g_Wb_hi);
    cudaGetSymbolAddress((void**)&Wbl,  g_Wb_lo);
    __nv_bfloat16* Wbh0 = Wbh;                __nv_bfloat16* Wbl0 = Wbl;
    __nv_bfloat16* Wbh1 = Wbh + DDIM*2*DDIM;  __nv_bfloat16* Wbl1 = Wbl + DDIM*2*DDIM;
    __nv_bfloat16* Wbh2 = Wbh + 2*DDIM*2*DDIM;__nv_bfloat16* Wbl2 = Wbl + 2*DDIM*2*DDIM;

    // weight bf16x2 splits
    const int cb = (DDIM * DDIM + 255) / 256;
    k_convert<<<cb, 256>>>(W_proj, Wph,  Wpl,  0,   128);
    k_convert<<<cb, 256>>>(W1_l,   Wbh0, Wbl0, 0,   256);
    k_convert<<<cb, 256>>>(W1_r,   Wbh0, Wbl0, 128, 256);
    k_convert<<<cb, 256>>>(W2_l,   Wbh1, Wbl1, 0,   256);
    k_convert<<<cb, 256>>>(W2_r,   Wbh1, Wbl1, 128, 256);
    k_convert<<<cb, 256>>>(W3_l,   Wbh2, Wbl2, 0,   256);
    k_convert<<<cb, 256>>>(W3_r,   Wbh2, Wbl2, 128, 256);

    // edge-index dtype detection + CSR build
    k_det_init<<<1, 1>>>();
    k_detect<<<(EE + 255) / 256, 256>>>((const unsigned*)ei);
    k_zero_deg<<<(NN + 255) / 256, 256>>>();
    k_hist<<<(EE + 255) / 256, 256>>>(ei);
    k_scan<<<1, 1024>>>();
    k_fill<<<(EE + 255) / 256, 256>>>(ei);

    const int aggBlocks = (NN + 7) / 8;   // warp per node, 8 warps/block

    // h0 = x @ Wproj^T
    k_gemm<1, 0><<<NBLK, 128>>>(x, x, Wph, Wpl, b1, x, bufA);

    // layer 1: h1 = relu([mean(h0)|h0] @ W1 + b1) + x
    k_aggregate<<<aggBlocks, 256>>>(bufA, bufM);
    k_gemm<2, 1><<<NBLK, 128>>>(bufM, bufA, Wbh0, Wbl0, b1, x, bufB);

    // layer 2: h2 = relu([mean(h1)|h1] @ W2 + b2) + h1
    k_aggregate<<<aggBlocks, 256>>>(bufB, bufM);
    k_gemm<2, 1><<<NBLK, 128>>>(bufM, bufB, Wbh1, Wbl1, b2, bufB, bufA);

    // layer 3: out = normalize([mean(h2)|h2] @ W3 + b3)
    k_aggregate<<<aggBlocks, 256>>>(bufA, bufM);
    k_gemm<2, 2><<<NBLK, 128>>>(bufM, bufA, Wbh2, Wbl2, b3, bufA, out);
}

// round 3
// speedup vs baseline: 1.3827x; 1.3827x over previous
#include <cuda_runtime.h>
#include <cuda_bf16.h>
#include <stdint.h>
#include <math.h>

#define NN   100000
#define EE   800000
#define DDIM 128
#define NPAD 100096   // 782 * 128
#define NBLK 782

// ---------------- scratch (device globals; no runtime alloc) ----------------
__device__ __align__(256) float g_bufA[(size_t)NPAD * DDIM];
__device__ __align__(256) float g_bufB[(size_t)NPAD * DDIM];
__device__ __align__(256) float g_bufM[(size_t)NPAD * DDIM];
__device__ int   g_deg[NN];
__device__ int   g_rowptr[NN + 1];
__device__ int   g_cursor[NN];
__device__ float g_deginv[NN];
__device__ int   g_colidx[EE];
__device__ int   g_is64;
// fragment-packed weights: hi+lo interleaved per 16B MMA fragment
// proj: 128 n-rows * 8 k-chunks * 4 tig * 4 u32  -> 16384 u32 = 64KB
// layer: 128 n-rows * 16 k-chunks * 4 tig * 4 u32 -> 32768 u32 = 128KB each
__device__ __align__(16) unsigned g_Wp[DDIM * 8 * 16];
__device__ __align__(16) unsigned g_Wb[3][DDIM * 16 * 16];

// ---------------- edge-index dtype detection + init ----------------
__global__ void k_init() {
    int i = blockIdx.x * blockDim.x + threadIdx.x;
    if (i < NN) g_deg[i] = 0;
    if (i == 0) g_is64 = 1;
}

__global__ void k_detect(const unsigned* __restrict__ w) {
    int i = blockIdx.x * blockDim.x + threadIdx.x;
    if (i < EE && w[2 * i + 1] != 0u) g_is64 = 0;
}

__device__ __forceinline__ int load_idx(const void* ei, int pos, int is64) {
    if (is64) return (int)((const long long*)ei)[pos];
    return ((const int*)ei)[pos];
}

// ---------------- CSR build ----------------
__global__ void k_hist(const void* __restrict__ ei) {
    int e = blockIdx.x * blockDim.x + threadIdx.x;
    if (e < EE) {
        int d = load_idx(ei, EE + e, g_is64);
        if ((unsigned)d < NN) atomicAdd(&g_deg[d], 1);
    }
}

__global__ void k_scan() {
    __shared__ int part[1024];
    const int t = threadIdx.x;
    int lo = t * 98; if (lo > NN) lo = NN;
    int hi = lo + 98; if (hi > NN) hi = NN;
    int s = 0;
    for (int i = lo; i < hi; i++) s += g_deg[i];
    part[t] = s;
    __syncthreads();
    for (int off = 1; off < 1024; off <<= 1) {
        int v = (t >= off) ? part[t - off] : 0;
        __syncthreads();
        part[t] += v;
        __syncthreads();
    }
    int run = (t == 0) ? 0 : part[t - 1];
    for (int i = lo; i < hi; i++) {
        int d = g_deg[i];
        g_rowptr[i] = run;
        g_cursor[i] = run;
        g_deginv[i] = (d > 0) ? 1.0f / (float)d : 0.0f;
        run += d;
    }
    if (t == 1023) g_rowptr[NN] = part[1023];
}

__global__ void k_fill(const void* __restrict__ ei) {
    int e = blockIdx.x * blockDim.x + threadIdx.x;
    if (e < EE) {
        int is64 = g_is64;
        int s = load_idx(ei, e, is64);
        int d = load_idx(ei, EE + e, is64);
        if ((unsigned)d < NN && (unsigned)s < NN) {
            int p = atomicAdd(&g_cursor[d], 1);
            g_colidx[p] = s;
        }
    }
}

// ---------------- scatter-mean as CSR gather-sum (warp per node) ----------------
__global__ void k_aggregate(const float* __restrict__ h, float* __restrict__ mean) {
    int node = (blockIdx.x * blockDim.x + threadIdx.x) >> 5;
    if (node >= NN) return;
    int lane = threadIdx.x & 31;
    int s = g_rowptr[node], e = g_rowptr[node + 1];
    float4 a0 = make_float4(0.f, 0.f, 0.f, 0.f);
    float4 a1 = make_float4(0.f, 0.f, 0.f, 0.f);
    int i = s;
    for (; i + 2 <= e; i += 2) {
        int j0 = g_colidx[i];
        int j1 = g_colidx[i + 1];
        float4 v0 = *(const float4*)(h + (size_t)j0 * DDIM + lane * 4);
        float4 v1 = *(const float4*)(h + (size_t)j1 * DDIM + lane * 4);
        a0.x += v0.x; a0.y += v0.y; a0.z += v0.z; a0.w += v0.w;
        a1.x += v1.x; a1.y += v1.y; a1.z += v1.z; a1.w += v1.w;
    }
    if (i < e) {
        int j0 = g_colidx[i];
        float4 v0 = *(const float4*)(h + (size_t)j0 * DDIM + lane * 4);
        a0.x += v0.x; a0.y += v0.y; a0.z += v0.z; a0.w += v0.w;
    }
    float sc = g_deginv[node];
    float4 r;
    r.x = (a0.x + a1.x) * sc;
    r.y = (a0.y + a1.y) * sc;
    r.z = (a0.z + a1.z) * sc;
    r.w = (a0.w + a1.w) * sc;
    *(float4*)(mean + (size_t)node * DDIM + lane * 4) = r;
}

// ---------------- weight conversion: fp32 -> fragment-packed bf16 hi/lo ----------------
// Fragment layout (u32 units): frag = ((n * (KF/16) + ksf) * 4 + tig) * 4
//   frag[0] = hi packed {W[n][kb], W[n][kb+1]}      kb = ksf*16 + tig*2
//   frag[1] = hi packed {W[n][kb+8], W[n][kb+9]}
//   frag[2] = lo packed (same cols as frag[0])
//   frag[3] = lo packed (same cols as frag[1])
struct ConvArgs {
    const float*  src[7];
    unsigned*     dst[7];
    int           koff[7];
    int           kfull[7];
};

__global__ void k_convert_all(ConvArgs a) {
    int m = blockIdx.y;
    int idx = blockIdx.x * blockDim.x + threadIdx.x;
    if (idx >= DDIM * DDIM) return;
    int n = idx >> 7, k = idx & 127;
    float v = a.src[m][idx];
    __nv_bfloat16 h = __float2bfloat16(v);
    __nv_bfloat16 l = __float2bfloat16(v - __bfloat162float(h));
    int kg   = a.koff[m] + k;
    int ksf  = kg >> 4;
    int kpos = kg & 15;
    int p    = kpos >> 1;
    int tig  = p & 3;
    int half = p >> 2;
    int b    = kpos & 1;
    unsigned fragbase = ((unsigned)(n * (a.kfull[m] >> 4) + ksf) * 4 + tig) * 4;
    __nv_bfloat16* d = (__nv_bfloat16*)a.dst[m];
    d[(fragbase + half) * 2 + b]     = h;
    d[(fragbase + 2 + half) * 2 + b] = l;
}

// ---------------- GEMM: C[N,128] = [A0 | A1][N,KH*128] @ B + epilogue ----------------
__device__ __forceinline__ unsigned pack2(__nv_bfloat16 a, __nv_bfloat16 b) {
    __nv_bfloat162 t = __halves2bfloat162(a, b);
    return *reinterpret_cast<unsigned*>(&t);
}

__device__ __forceinline__ void split2(float x, float y, unsigned& hi, unsigned& lo) {
    __nv_bfloat16 hx = __float2bfloat16(x);
    __nv_bfloat16 hy = __float2bfloat16(y);
    hi = pack2(hx, hy);
    lo = pack2(__float2bfloat16(x - __bfloat162float(hx)),
               __float2bfloat16(y - __bfloat162float(hy)));
}

__device__ __forceinline__ void mma_bf16(float (&c)[4], const unsigned (&a)[4],
                                         unsigned b0, unsigned b1) {
    asm volatile(
        "mma.sync.aligned.m16n8k16.row.col.f32.bf16.bf16.f32 "
        "{%0,%1,%2,%3}, {%4,%5,%6,%7}, {%8,%9}, {%0,%1,%2,%3};\n"
        : "+f"(c[0]), "+f"(c[1]), "+f"(c[2]), "+f"(c[3])
        : "r"(a[0]), "r"(a[1]), "r"(a[2]), "r"(a[3]), "r"(b0), "r"(b1));
}

// EPI: 0 = plain store, 1 = relu(acc+bias)+identity, 2 = bias + row L2-normalize
template<int KH, int EPI>
__global__ void __launch_bounds__(128, 2) k_gemm(
    const float* __restrict__ A0, const float* __restrict__ A1,
    const unsigned* __restrict__ Bfrag,
    const float* __restrict__ bias, const float* __restrict__ identity,
    float* __restrict__ out)
{
    constexpr int KFULL = KH * 128;
    constexpr int KCH   = KFULL / 16;   // k-chunks
    const int w = threadIdx.x >> 5;
    const int lane = threadIdx.x & 31;
    const int g = lane >> 2;
    const int tig = lane & 3;
    const int rowbase = blockIdx.x * 128 + w * 32;
    int rr[4] = { rowbase + g, rowbase + g + 8, rowbase + g + 16, rowbase + g + 24 };
    bool pp[4];
#pragma unroll
    for (int i = 0; i < 4; i++) pp[i] = rr[i] < NN;

    const uint4* Bf = (const uint4*)Bfrag;
    // uint4 index for (nr, ksf) = (nr * KCH + ksf) * 4 + tig
    const int bbase = g * KCH * 4 + tig;

    float acc[16][2][4];
#pragma unroll
    for (int t = 0; t < 16; t++)
#pragma unroll
        for (int s = 0; s < 2; s++)
#pragma unroll
            for (int i = 0; i < 4; i++) acc[t][s][i] = 0.f;

#pragma unroll
    for (int kh = 0; kh < KH; kh++) {
        const float* A = (kh == 0) ? A0 : A1;
#pragma unroll
        for (int ks = 0; ks < 8; ks++) {
            const int ksf = kh * 8 + ks;
            const int kc = ks * 16 + tig * 2;
            unsigned aH[2][4], aL[2][4];
#pragma unroll
            for (int s = 0; s < 2; s++) {
                float2 z = make_float2(0.f, 0.f);
                float2 v00 = pp[2*s]   ? *(const float2*)(A + (size_t)rr[2*s]   * DDIM + kc)     : z;
                float2 v01 = pp[2*s]   ? *(const float2*)(A + (size_t)rr[2*s]   * DDIM + kc + 8) : z;
                float2 v10 = pp[2*s+1] ? *(const float2*)(A + (size_t)rr[2*s+1] * DDIM + kc)     : z;
                float2 v11 = pp[2*s+1] ? *(const float2*)(A + (size_t)rr[2*s+1] * DDIM + kc + 8) : z;
                split2(v00.x, v00.y, aH[s][0], aL[s][0]);
                split2(v10.x, v10.y, aH[s][1], aL[s][1]);
                split2(v01.x, v01.y, aH[s][2], aL[s][2]);
                split2(v11.x, v11.y, aH[s][3], aL[s][3]);
            }
#pragma unroll
            for (int t = 0; t < 16; t++) {
                uint4 bb = Bf[bbase + t * 8 * KCH * 4 + ksf * 4];
                mma_bf16(acc[t][0], aH[0], bb.x, bb.y);
                mma_bf16(acc[t][0], aH[0], bb.z, bb.w);
                mma_bf16(acc[t][0], aL[0], bb.x, bb.y);
                mma_bf16(acc[t][1], aH[1], bb.x, bb.y);
                mma_bf16(acc[t][1], aH[1], bb.z, bb.w);
                mma_bf16(acc[t][1], aL[1], bb.x, bb.y);
            }
        }
    }

    if (EPI == 0) {
#pragma unroll
        for (int t = 0; t < 16; t++) {
            const int c = t * 8 + tig * 2;
#pragma unroll
            for (int s = 0; s < 2; s++) {
                if (pp[2*s])
                    *(float2*)(out + (size_t)rr[2*s] * DDIM + c) =
                        make_float2(acc[t][s][0], acc[t][s][1]);
                if (pp[2*s+1])
                    *(float2*)(out + (size_t)rr[2*s+1] * DDIM + c) =
                        make_float2(acc[t][s][2], acc[t][s][3]);
            }
        }
    } else if (EPI == 1) {
#pragma unroll
        for (int t = 0; t < 16; t++) {
            const int c = t * 8 + tig * 2;
            float2 bb = *(const float2*)(bias + c);
#pragma unroll
            for (int s = 0; s < 2; s++) {
                if (pp[2*s]) {
                    float vx = fmaxf(acc[t][s][0] + bb.x, 0.f);
                    float vy = fmaxf(acc[t][s][1] + bb.y, 0.f);
                    float2 id = *(const float2*)(identity + (size_t)rr[2*s] * DDIM + c);
                    *(float2*)(out + (size_t)rr[2*s] * DDIM + c) =
                        make_float2(vx + id.x, vy + id.y);
                }
                if (pp[2*s+1]) {
                    float vx = fmaxf(acc[t][s][2] + bb.x, 0.f);
                    float vy = fmaxf(acc[t][s][3] + bb.y, 0.f);
                    float2 id = *(const float2*)(identity + (size_t)rr[2*s+1] * DDIM + c);
                    *(float2*)(out + (size_t)rr[2*s+1] * DDIM + c) =
                        make_float2(vx + id.x, vy + id.y);
                }
            }
        }
    } else {
        float ss[4] = {0.f, 0.f, 0.f, 0.f};
#pragma unroll
        for (int t = 0; t < 16; t++) {
            const int c = t * 8 + tig * 2;
            float2 bb = *(const float2*)(bias + c);
#pragma unroll
            for (int s = 0; s < 2; s++) {
                acc[t][s][0] += bb.x; acc[t][s][1] += bb.y;
                acc[t][s][2] += bb.x; acc[t][s][3] += bb.y;
                ss[2*s]   += acc[t][s][0] * acc[t][s][0] + acc[t][s][1] * acc[t][s][1];
                ss[2*s+1] += acc[t][s][2] * acc[t][s][2] + acc[t][s][3] * acc[t][s][3];
            }
        }
#pragma unroll
        for (int i = 0; i < 4; i++) {
            ss[i] += __shfl_xor_sync(0xffffffffu, ss[i], 1);
            ss[i] += __shfl_xor_sync(0xffffffffu, ss[i], 2);
            ss[i] = 1.f / fmaxf(sqrtf(ss[i]), 1e-12f);
        }
#pragma unroll
        for (int t = 0; t < 16; t++) {
            const int c = t * 8 + tig * 2;
#pragma unroll
            for (int s = 0; s < 2; s++) {
                if (pp[2*s])
                    *(float2*)(out + (size_t)rr[2*s] * DDIM + c) =
                        make_float2(acc[t][s][0] * ss[2*s], acc[t][s][1] * ss[2*s]);
                if (pp[2*s+1])
                    *(float2*)(out + (size_t)rr[2*s+1] * DDIM + c) =
                        make_float2(acc[t][s][2] * ss[2*s+1], acc[t][s][3] * ss[2*s+1]);
            }
        }
    }
}

// ---------------- launch ----------------
extern "C" void kernel_launch(void* const* d_in, const int* in_sizes, int n_in,
                              void* d_out, int out_size) {
    const float* x      = (const float*)d_in[0];
    const void*  ei     = d_in[1];
    const float* W_proj = (const float*)d_in[2];
    const float* W1_l   = (const float*)d_in[3];
    const float* b1     = (const float*)d_in[4];
    const float* W1_r   = (const float*)d_in[5];
    const float* W2_l   = (const float*)d_in[6];
    const float* b2     = (const float*)d_in[7];
    const float* W2_r   = (const float*)d_in[8];
    const float* W3_l   = (const float*)d_in[9];
    const float* b3     = (const float*)d_in[10];
    const float* W3_r   = (const float*)d_in[11];
    float* out = (float*)d_out;

    float *bufA, *bufB, *bufM;
    unsigned *Wp, *Wb;
    cudaGetSymbolAddress((void**)&bufA, g_bufA);
    cudaGetSymbolAddress((void**)&bufB, g_bufB);
    cudaGetSymbolAddress((void**)&bufM, g_bufM);
    cudaGetSymbolAddress((void**)&Wp,   g_Wp);
    cudaGetSymbolAddress((void**)&Wb,   g_Wb);
    unsigned* Wb0 = Wb;
    unsigned* Wb1 = Wb + DDIM * 16 * 16;
    unsigned* Wb2 = Wb + 2 * DDIM * 16 * 16;

    // 1: fused weight conversion (fragment packing)
    ConvArgs ca;
    ca.src[0] = W_proj; ca.dst[0] = Wp;  ca.koff[0] = 0;   ca.kfull[0] = 128;
    ca.src[1] = W1_l;   ca.dst[1] = Wb0; ca.koff[1] = 0;   ca.kfull[1] = 256;
    ca.src[2] = W1_r;   ca.dst[2] = Wb0; ca.koff[2] = 128; ca.kfull[2] = 256;
    ca.src[3] = W2_l;   ca.dst[3] = Wb1; ca.koff[3] = 0;   ca.kfull[3] = 256;
    ca.src[4] = W2_r;   ca.dst[4] = Wb1; ca.koff[4] = 128; ca.kfull[4] = 256;
    ca.src[5] = W3_l;   ca.dst[5] = Wb2; ca.koff[5] = 0;   ca.kfull[5] = 256;
    ca.src[6] = W3_r;   ca.dst[6] = Wb2; ca.koff[6] = 128; ca.kfull[6] = 256;
    k_convert_all<<<dim3(64, 7), 256>>>(ca);

    // 2-5: init, detect dtype, degree histogram, prefix scan
    k_init<<<(NN + 255) / 256, 256>>>();
    k_detect<<<(EE + 255) / 256, 256>>>((const unsigned*)ei);
    k_hist<<<(EE + 255) / 256, 256>>>(ei);
    k_scan<<<1, 1024>>>();

    // 6: proj GEMM (positioned 6th so ncu -s 5 -c 1 profiles it)
    k_gemm<1, 0><<<NBLK, 128>>>(x, x, Wp, b1, x, bufA);

    // 7: CSR fill
    k_fill<<<(EE + 255) / 256, 256>>>(ei);

    const int aggBlocks = (NN + 7) / 8;   // warp per node, 8 warps/block

    // layer 1: h1 = relu([mean(h0)|h0] @ W1 + b1) + x
    k_aggregate<<<aggBlocks, 256>>>(bufA, bufM);
    k_gemm<2, 1><<<NBLK, 128>>>(bufM, bufA, Wb0, b1, x, bufB);

    // layer 2: h2 = relu([mean(h1)|h1] @ W2 + b2) + h1
    k_aggregate<<<aggBlocks, 256>>>(bufB, bufM);
    k_gemm<2, 1><<<NBLK, 128>>>(bufM, bufB, Wb1, b2, bufB, bufA);

    // layer 3: out = normalize([mean(h2)|h2] @ W3 + b3)
    k_aggregate<<<aggBlocks, 256>>>(bufA, bufM);
    k_gemm<2, 2><<<NBLK, 128>>>(bufM, bufA, Wb2, b3, bufA, out);
}